// round 15
// baseline (speedup 1.0000x reference)
#include <cuda_runtime.h>
#include <cuda_bf16.h>
#include <stdint.h>
#include <math.h>

// ---------------------------------------------------------------------------
// LN-LSTM cell.  B=4096, IN=1024, H=2048, OUT=1024.
// GEMMs via mma.sync bf16 (HMMA), split precision [hi|lo] (2K) + 3-pass remap.
// R15: GEMM uses 4 warps of 64x64 (2x2 grid) instead of 8x(64x32) -> smem
// fragment traffic per kt drops 96KB->64KB/CTA, un-saturating the crossbar.
// CTA tile 128x128x64, 3-stage cp.async, 2 CTA/SM preserved.
// ---------------------------------------------------------------------------

#define BDIM 4096
#define HDIM 2048
#define EPS_LN 1e-5f

__device__ float g_Xbuf[(size_t)BDIM * 4 * HDIM];
__device__ float g_Hbuf[(size_t)BDIM * 4 * HDIM];
__device__ __nv_bfloat16 g_Ax[(size_t)BDIM * 2 * 1024];
__device__ __nv_bfloat16 g_Ah[(size_t)BDIM * 2 * HDIM];
__device__ __nv_bfloat16 g_Wx[(size_t)4 * HDIM * 2 * 1024];
__device__ __nv_bfloat16 g_Wh[(size_t)4 * HDIM * 2 * HDIM];
__device__ __nv_bfloat16 g_Wd[(size_t)1024 * 2 * HDIM];
__device__ __nv_bfloat16 g_Hxc[(size_t)BDIM * 2 * HDIM];
__device__ float g_biasx[4 * HDIM];
__device__ float g_biash[4 * HDIM];

// ------------------------------- helpers -----------------------------------
__device__ __forceinline__ uint32_t smem_u32(const void* p) {
    uint32_t a;
    asm("{ .reg .u64 t; cvta.to.shared.u64 t, %1; cvt.u32.u64 %0, t; }" : "=r"(a) : "l"(p));
    return a;
}
#define CP_ASYNC16(dst, src) \
    asm volatile("cp.async.cg.shared.global [%0], [%1], 16;" :: "r"(dst), "l"(src) : "memory")
#define CP_COMMIT()  asm volatile("cp.async.commit_group;" ::: "memory")
#define CP_WAIT1()   asm volatile("cp.async.wait_group 1;" ::: "memory")

__device__ __forceinline__ uint32_t pack_bf2(float a, float b) {
    const uint32_t ua = (uint32_t)__bfloat16_as_ushort(__float2bfloat16(a));
    const uint32_t ub = (uint32_t)__bfloat16_as_ushort(__float2bfloat16(b));
    return ua | (ub << 16);
}
__device__ __forceinline__ void split4(const float4 x, uint2& hi, uint2& lo) {
    const __nv_bfloat16 h0 = __float2bfloat16(x.x), h1 = __float2bfloat16(x.y);
    const __nv_bfloat16 h2 = __float2bfloat16(x.z), h3 = __float2bfloat16(x.w);
    hi.x = (uint32_t)__bfloat16_as_ushort(h0) | ((uint32_t)__bfloat16_as_ushort(h1) << 16);
    hi.y = (uint32_t)__bfloat16_as_ushort(h2) | ((uint32_t)__bfloat16_as_ushort(h3) << 16);
    lo.x = pack_bf2(x.x - __bfloat162float(h0), x.y - __bfloat162float(h1));
    lo.y = pack_bf2(x.z - __bfloat162float(h2), x.w - __bfloat162float(h3));
}

// ---------------------------------------------------------------------------
// HMMA GEMM body.  128 threads = 4 warps in 2x2 grid of 64x64 warp tiles.
// A is [M, 2*K0] = [hi|lo]; W is [Ntot, 2*K0] = [hi|lo]; 3-pass K remap.
// ---------------------------------------------------------------------------
#define BM 128
#define BN 128
#define BK 64
#define NSTG 3
#define STG_BYTES 32768                 // A(16KB) + B(16KB)
#define GEMM_SMEM (NSTG * STG_BYTES)    // 98304

__device__ __forceinline__ void gemm_body(
    const __nv_bfloat16* __restrict__ A, const __nv_bfloat16* __restrict__ W,
    const float* __restrict__ bias, float* __restrict__ C, int K0, int Ntot,
    int bm, int bn)
{
    extern __shared__ char smem[];
    const uint32_t sb = smem_u32(smem);
    const int tid  = threadIdx.x;
    const int lane = tid & 31, wid = tid >> 5;
    const int wm = wid & 1, wn = wid >> 1;            // warp grid 2 x 2 (64x64)
    const int m0 = bm * BM, n0 = bn * BN;
    const int K0B = K0 / BK;
    const int nkt = 3 * K0B;
    const int Kcat = 2 * K0;

    // cp.async: 128 threads, one A row + one B row each, 8x16B chunks per row
    const __nv_bfloat16* agp = A + (size_t)(m0 + tid) * Kcat;
    const __nv_bfloat16* bgp = W + (size_t)(n0 + tid) * Kcat;

#define LOADT(kt, stg) do {                                                     \
    const int _p = (kt) / K0B, _r = (kt) - _p * K0B;                            \
    const int _ak = (_p == 1) ? K0B + _r : _r;                                  \
    const int _wk = (_p == 2) ? K0B + _r : _r;                                  \
    const __nv_bfloat16* a_ = agp + (size_t)_ak * BK;                           \
    const __nv_bfloat16* b_ = bgp + (size_t)_wk * BK;                           \
    const uint32_t as_ = sb + (stg) * STG_BYTES;                                \
    const uint32_t bs_ = as_ + 16384;                                           \
    _Pragma("unroll")                                                           \
    for (int j = 0; j < 8; j++) {                                               \
        const uint32_t off = tid * 128 + (((uint32_t)j ^ (tid & 7)) << 4);      \
        CP_ASYNC16(as_ + off, a_ + j * 8);                                      \
        CP_ASYNC16(bs_ + off, b_ + j * 8);                                      \
    }                                                                           \
} while (0)

    // ldmatrix addressing
    const int a_r16 = lane & 15;
    const int a_h   = lane >> 4;
    const int b_sel = lane >> 3, b_tr = lane & 7;
    const int b_roff = ((b_sel >> 1) & 1) * 8 + b_tr;
    const int b_h    = b_sel & 1;

    float acc[4][8][4];
    #pragma unroll
    for (int i = 0; i < 4; i++)
        #pragma unroll
        for (int j = 0; j < 8; j++)
            #pragma unroll
            for (int q = 0; q < 4; q++) acc[i][j][q] = 0.0f;

    LOADT(0, 0); CP_COMMIT();
    LOADT(1, 1); CP_COMMIT();

    for (int kt = 0; kt < nkt; kt++) {
        const int stg = kt % NSTG;
        CP_WAIT1();
        __syncthreads();
        const uint32_t as_ = sb + stg * STG_BYTES;
        const uint32_t bs_ = as_ + 16384;

        #pragma unroll
        for (int kk = 0; kk < 4; kk++) {
            uint32_t a[4][4], b[4][4];
            #pragma unroll
            for (int mf = 0; mf < 4; mf++) {
                const int r = wm * 64 + mf * 16 + a_r16;
                const uint32_t ad = as_ + r * 128 + (((kk * 2 + a_h) ^ (r & 7)) << 4);
                asm volatile("ldmatrix.sync.aligned.m8n8.x4.shared.b16 {%0,%1,%2,%3}, [%4];"
                    : "=r"(a[mf][0]), "=r"(a[mf][1]), "=r"(a[mf][2]), "=r"(a[mf][3])
                    : "r"(ad));
            }
            #pragma unroll
            for (int p = 0; p < 4; p++) {
                const int r = wn * 64 + p * 16 + b_roff;
                const uint32_t bd = bs_ + r * 128 + (((kk * 2 + b_h) ^ (r & 7)) << 4);
                asm volatile("ldmatrix.sync.aligned.m8n8.x4.shared.b16 {%0,%1,%2,%3}, [%4];"
                    : "=r"(b[p][0]), "=r"(b[p][1]), "=r"(b[p][2]), "=r"(b[p][3])
                    : "r"(bd));
            }
            #pragma unroll
            for (int mf = 0; mf < 4; mf++)
                #pragma unroll
                for (int nf = 0; nf < 8; nf++) {
                    const uint32_t b0 = b[nf >> 1][(nf & 1) * 2 + 0];
                    const uint32_t b1 = b[nf >> 1][(nf & 1) * 2 + 1];
                    asm volatile(
                        "mma.sync.aligned.m16n8k16.row.col.f32.bf16.bf16.f32 "
                        "{%0,%1,%2,%3}, {%4,%5,%6,%7}, {%8,%9}, {%0,%1,%2,%3};"
                        : "+f"(acc[mf][nf][0]), "+f"(acc[mf][nf][1]),
                          "+f"(acc[mf][nf][2]), "+f"(acc[mf][nf][3])
                        : "r"(a[mf][0]), "r"(a[mf][1]), "r"(a[mf][2]), "r"(a[mf][3]),
                          "r"(b0), "r"(b1));
                }
        }
        if (kt + NSTG - 1 < nkt) LOADT(kt + NSTG - 1, (kt + NSTG - 1) % NSTG);
        CP_COMMIT();
    }

    // epilogue: bias + store
    const int er = lane >> 2, ec = (lane & 3) * 2;
    #pragma unroll
    for (int mf = 0; mf < 4; mf++) {
        const int grow = m0 + wm * 64 + mf * 16 + er;
        #pragma unroll
        for (int nf = 0; nf < 8; nf++) {
            const int gcol = n0 + wn * 64 + nf * 8 + ec;
            const float bx0 = __ldg(bias + gcol), bx1 = __ldg(bias + gcol + 1);
            float2 v0 = make_float2(acc[mf][nf][0] + bx0, acc[mf][nf][1] + bx1);
            float2 v1 = make_float2(acc[mf][nf][2] + bx0, acc[mf][nf][3] + bx1);
            *(float2*)&C[(size_t)grow * Ntot + gcol] = v0;
            *(float2*)&C[(size_t)(grow + 8) * Ntot + gcol] = v1;
        }
    }
#undef LOADT
}

__global__ void __launch_bounds__(128, 2) gemm_dual(
    const __nv_bfloat16* __restrict__ Ah, const __nv_bfloat16* __restrict__ Wh,
    const float* __restrict__ biash, float* __restrict__ Hbuf,
    const __nv_bfloat16* __restrict__ Ax, const __nv_bfloat16* __restrict__ Wx,
    const float* __restrict__ biasx, float* __restrict__ Xbuf)
{
    int idx = blockIdx.x;
    if (idx < 2048) {
        gemm_body(Ah, Wh, biash, Hbuf, HDIM, 4 * HDIM, idx & 31, idx >> 5);
    } else {
        idx -= 2048;
        gemm_body(Ax, Wx, biasx, Xbuf, 1024, 4 * HDIM, idx & 31, idx >> 5);
    }
}

__global__ void __launch_bounds__(128, 2) gemm_single(
    const __nv_bfloat16* __restrict__ A, const __nv_bfloat16* __restrict__ W,
    const float* __restrict__ bias, float* __restrict__ C, int K0, int Ntot)
{
    const int idx = blockIdx.x;
    gemm_body(A, W, bias, C, K0, Ntot, idx & 31, idx >> 5);
}

// ---------------------------------------------------------------------------
// Prep: all fp32 -> bf16 [hi|lo] splits + bias concats, float4 vectorized.
// ---------------------------------------------------------------------------
#define PREP_BLOCKS 25664

__device__ __forceinline__ void split_row_v4(
    const float* __restrict__ src, __nv_bfloat16* __restrict__ d, int K)
{
    for (int c = threadIdx.x * 4; c < K; c += 1024) {
        const float4 x = *(const float4*)(src + c);
        uint2 hi, lo;
        split4(x, hi, lo);
        *(uint2*)(d + c) = hi;
        *(uint2*)(d + K + c) = lo;
    }
}

__global__ void __launch_bounds__(256) prep_kernel(
    const float* __restrict__ inp, const float* __restrict__ h0,
    const float* __restrict__ Wdec,
    const float* __restrict__ Wfx, const float* __restrict__ Wix,
    const float* __restrict__ Wcx, const float* __restrict__ Wox,
    const float* __restrict__ Wfh, const float* __restrict__ Wih,
    const float* __restrict__ Wch, const float* __restrict__ Woh,
    const float* __restrict__ bfx, const float* __restrict__ bix,
    const float* __restrict__ bcx, const float* __restrict__ box_,
    const float* __restrict__ bfh, const float* __restrict__ bih,
    const float* __restrict__ bch, const float* __restrict__ boh,
    __nv_bfloat16* __restrict__ Ax, __nv_bfloat16* __restrict__ Ah,
    __nv_bfloat16* __restrict__ Wd, __nv_bfloat16* __restrict__ Wx,
    __nv_bfloat16* __restrict__ Wh,
    float* __restrict__ biasx, float* __restrict__ biash)
{
    int b = blockIdx.x;
    if (b < 4096) {
        split_row_v4(inp + (size_t)b * 1024, Ax + (size_t)b * 2048, 1024);
        return;
    }
    b -= 4096;
    if (b < 4096) {
        split_row_v4(h0 + (size_t)b * 2048, Ah + (size_t)b * 4096, 2048);
        return;
    }
    b -= 4096;
    if (b < 1024) {
        split_row_v4(Wdec + (size_t)b * 2048, Wd + (size_t)b * 4096, 2048);
        return;
    }
    b -= 1024;
    if (b < 8192) {
        const int gate = b >> 11, row = b & 2047;
        const float* w = (gate == 0) ? Wfx : (gate == 1) ? Wix : (gate == 2) ? Wcx : Wox;
        split_row_v4(w + (size_t)row * 1024, Wx + (size_t)b * 2048, 1024);
        return;
    }
    b -= 8192;
    if (b < 8192) {
        const int gate = b >> 11, row = b & 2047;
        const float* w = (gate == 0) ? Wfh : (gate == 1) ? Wih : (gate == 2) ? Wch : Woh;
        split_row_v4(w + (size_t)row * 2048, Wh + (size_t)b * 4096, 2048);
        return;
    }
    b -= 8192;
    if (b < 32) {
        const int i = b * 256 + threadIdx.x;
        const int g = i >> 11, c = i & 2047;
        biasx[i] = (g == 0) ? bfx[c] : (g == 1) ? bix[c] : (g == 2) ? bcx[c] : box_[c];
        return;
    }
    b -= 32;
    {
        const int i = b * 256 + threadIdx.x;
        const int g = i >> 11, c = i & 2047;
        biash[i] = (g == 0) ? bfh[c] : (g == 1) ? bih[c] : (g == 2) ? bch[c] : boh[c];
    }
}

// ---------------------------------------------------------------------------
// LN combine (float4): G = LN(X;ax,bx) + LN(H;ah,bh), in place into Xbuf.
// ---------------------------------------------------------------------------
__global__ void __launch_bounds__(256) ln_combine_kernel(
    float* __restrict__ Xbuf, const float* __restrict__ Hbuf,
    const float* __restrict__ ax, const float* __restrict__ bxv,
    const float* __restrict__ ah, const float* __restrict__ bhv)
{
    const int row = blockIdx.x, gate = blockIdx.y, tid = threadIdx.x;
    const size_t base = (size_t)row * (4 * HDIM) + (size_t)gate * HDIM;

    float4 x[2], h[2];
    float sx = 0.f, sxx = 0.f, sh = 0.f, shh = 0.f;
    #pragma unroll
    for (int i = 0; i < 2; i++) {
        const int c = i * 1024 + tid * 4;
        x[i] = *(const float4*)(Xbuf + base + c);
        h[i] = *(const float4*)(Hbuf + base + c);
        sx += x[i].x + x[i].y + x[i].z + x[i].w;
        sxx += x[i].x * x[i].x + x[i].y * x[i].y + x[i].z * x[i].z + x[i].w * x[i].w;
        sh += h[i].x + h[i].y + h[i].z + h[i].w;
        shh += h[i].x * h[i].x + h[i].y * h[i].y + h[i].z * h[i].z + h[i].w * h[i].w;
    }
    __shared__ float4 red[256];
    red[tid] = make_float4(sx, sxx, sh, shh);
    __syncthreads();
    #pragma unroll
    for (int s = 128; s > 0; s >>= 1) {
        if (tid < s) {
            float4 o = red[tid + s], m = red[tid];
            red[tid] = make_float4(m.x + o.x, m.y + o.y, m.z + o.z, m.w + o.w);
        }
        __syncthreads();
    }
    const float4 t = red[0];
    const float n = (float)HDIM;
    const float mux = t.x / n, muh = t.z / n;
    const float vx = (t.y - n * mux * mux) / (n - 1.0f);
    const float vh = (t.w - n * muh * muh) / (n - 1.0f);
    const float rx = 1.0f / (sqrtf(fmaxf(vx, 0.f)) + EPS_LN);
    const float rh = 1.0f / (sqrtf(fmaxf(vh, 0.f)) + EPS_LN);
    #pragma unroll
    for (int i = 0; i < 2; i++) {
        const int c = i * 1024 + tid * 4;
        const float4 a4 = *(const float4*)(ax + c);
        const float4 b4 = *(const float4*)(bxv + c);
        const float4 a4h = *(const float4*)(ah + c);
        const float4 b4h = *(const float4*)(bhv + c);
        float4 g;
        g.x = (x[i].x - mux) * rx * a4.x + b4.x + (h[i].x - muh) * rh * a4h.x + b4h.x;
        g.y = (x[i].y - mux) * rx * a4.y + b4.y + (h[i].y - muh) * rh * a4h.y + b4h.y;
        g.z = (x[i].z - mux) * rx * a4.z + b4.z + (h[i].z - muh) * rh * a4h.z + b4h.z;
        g.w = (x[i].w - mux) * rx * a4.w + b4.w + (h[i].w - muh) * rh * a4h.w + b4h.w;
        *(float4*)(Xbuf + base + c) = g;
    }
}

// ---------------------------------------------------------------------------
// Cell (float4): gates -> cx, row-LN(cx), hx; emits hx split [hi|lo] bf16.
// ---------------------------------------------------------------------------
__global__ void __launch_bounds__(256) cell_kernel(
    const float* __restrict__ G, const float* __restrict__ c0,
    const float* __restrict__ ac, const float* __restrict__ bcv,
    float* __restrict__ hx_out, float* __restrict__ cx_out,
    __nv_bfloat16* __restrict__ hxcat)
{
    const int row = blockIdx.x, tid = threadIdx.x;
    const size_t base = (size_t)row * (4 * HDIM);

    float4 cv[2], og[2];
    float s = 0.f, ss = 0.f;
    #pragma unroll
    for (int i = 0; i < 2; i++) {
        const int c = i * 1024 + tid * 4;
        const float4 gf = *(const float4*)(G + base + c);
        const float4 gi = *(const float4*)(G + base + HDIM + c);
        const float4 gc = *(const float4*)(G + base + 2 * HDIM + c);
        const float4 go = *(const float4*)(G + base + 3 * HDIM + c);
        const float4 cz = *(const float4*)(c0 + (size_t)row * HDIM + c);
        float4 v;
        v.x = (1.0f / (1.0f + expf(-gf.x))) * cz.x + (1.0f / (1.0f + expf(-gi.x))) * tanhf(gc.x);
        v.y = (1.0f / (1.0f + expf(-gf.y))) * cz.y + (1.0f / (1.0f + expf(-gi.y))) * tanhf(gc.y);
        v.z = (1.0f / (1.0f + expf(-gf.z))) * cz.z + (1.0f / (1.0f + expf(-gi.z))) * tanhf(gc.z);
        v.w = (1.0f / (1.0f + expf(-gf.w))) * cz.w + (1.0f / (1.0f + expf(-gi.w))) * tanhf(gc.w);
        cv[i] = v; og[i] = go;
        s += v.x + v.y + v.z + v.w;
        ss += v.x * v.x + v.y * v.y + v.z * v.z + v.w * v.w;
    }
    __shared__ float2 red[256];
    red[tid] = make_float2(s, ss);
    __syncthreads();
    #pragma unroll
    for (int st = 128; st > 0; st >>= 1) {
        if (tid < st) {
            float2 o = red[tid + st], m = red[tid];
            red[tid] = make_float2(m.x + o.x, m.y + o.y);
        }
        __syncthreads();
    }
    const float2 t = red[0];
    const float n = (float)HDIM;
    const float mu = t.x / n;
    const float var = (t.y - n * mu * mu) / (n - 1.0f);
    const float rs = 1.0f / (sqrtf(fmaxf(var, 0.f)) + EPS_LN);

    __nv_bfloat16* hrow = hxcat + (size_t)row * (2 * HDIM);
    #pragma unroll
    for (int i = 0; i < 2; i++) {
        const int c = i * 1024 + tid * 4;
        const float4 a4 = *(const float4*)(ac + c);
        const float4 b4 = *(const float4*)(bcv + c);
        float4 hv;
        hv.x = (1.0f / (1.0f + expf(-og[i].x))) * tanhf((cv[i].x - mu) * rs * a4.x + b4.x);
        hv.y = (1.0f / (1.0f + expf(-og[i].y))) * tanhf((cv[i].y - mu) * rs * a4.y + b4.y);
        hv.z = (1.0f / (1.0f + expf(-og[i].z))) * tanhf((cv[i].z - mu) * rs * a4.z + b4.z);
        hv.w = (1.0f / (1.0f + expf(-og[i].w))) * tanhf((cv[i].w - mu) * rs * a4.w + b4.w);
        *(float4*)(hx_out + (size_t)row * HDIM + c) = hv;
        *(float4*)(cx_out + (size_t)row * HDIM + c) = cv[i];
        uint2 hi, lo;
        split4(hv, hi, lo);
        *(uint2*)(hrow + c) = hi;
        *(uint2*)(hrow + HDIM + c) = lo;
    }
}

// ---------------------------------------------------------------------------
extern "C" void kernel_launch(void* const* d_in, const int* in_sizes, int n_in,
                              void* d_out, int out_size)
{
    (void)in_sizes; (void)n_in; (void)out_size;
    const float* inp = (const float*)d_in[0];
    const float* h0  = (const float*)d_in[1];
    const float* c0  = (const float*)d_in[2];
    const float* Wfh = (const float*)d_in[3];   const float* bfh = (const float*)d_in[4];
    const float* Wih = (const float*)d_in[5];   const float* bih = (const float*)d_in[6];
    const float* Wch = (const float*)d_in[7];   const float* bch = (const float*)d_in[8];
    const float* Woh = (const float*)d_in[9];   const float* boh = (const float*)d_in[10];
    const float* Wfx = (const float*)d_in[11];  const float* bfx = (const float*)d_in[12];
    const float* Wix = (const float*)d_in[13];  const float* bix = (const float*)d_in[14];
    const float* Wcx = (const float*)d_in[15];  const float* bcx = (const float*)d_in[16];
    const float* Wox = (const float*)d_in[17];  const float* box_ = (const float*)d_in[18];
    const float* Wdec = (const float*)d_in[19]; const float* bdec = (const float*)d_in[20];
    const float* ax = (const float*)d_in[21];   const float* bx = (const float*)d_in[22];
    const float* ah = (const float*)d_in[23];   const float* bh = (const float*)d_in[24];
    const float* ac = (const float*)d_in[25];   const float* bc = (const float*)d_in[26];

    float *Xbuf, *Hbuf, *biasx, *biash;
    __nv_bfloat16 *Ax, *Ah, *Wx, *Wh, *Wd, *Hxc;
    cudaGetSymbolAddress((void**)&Xbuf, g_Xbuf);
    cudaGetSymbolAddress((void**)&Hbuf, g_Hbuf);
    cudaGetSymbolAddress((void**)&Ax, g_Ax);
    cudaGetSymbolAddress((void**)&Ah, g_Ah);
    cudaGetSymbolAddress((void**)&Wx, g_Wx);
    cudaGetSymbolAddress((void**)&Wh, g_Wh);
    cudaGetSymbolAddress((void**)&Wd, g_Wd);
    cudaGetSymbolAddress((void**)&Hxc, g_Hxc);
    cudaGetSymbolAddress((void**)&biasx, g_biasx);
    cudaGetSymbolAddress((void**)&biash, g_biash);

    cudaFuncSetAttribute(gemm_dual,   cudaFuncAttributeMaxDynamicSharedMemorySize, GEMM_SMEM);
    cudaFuncSetAttribute(gemm_single, cudaFuncAttributeMaxDynamicSharedMemorySize, GEMM_SMEM);

    float* out = (float*)d_out;
    float* hx  = out + (size_t)BDIM * 1024;
    float* cx  = hx + (size_t)BDIM * HDIM;

    prep_kernel<<<PREP_BLOCKS, 256>>>(
        inp, h0, Wdec,
        Wfx, Wix, Wcx, Wox, Wfh, Wih, Wch, Woh,
        bfx, bix, bcx, box_, bfh, bih, bch, boh,
        Ax, Ah, Wd, Wx, Wh, biasx, biash);

    gemm_dual<<<4096, 128, GEMM_SMEM>>>(
        Ah, Wh, biash, Hbuf, Ax, Wx, biasx, Xbuf);

    ln_combine_kernel<<<dim3(BDIM, 4), 256>>>(Xbuf, Hbuf, ax, bx, ah, bh);
    cell_kernel<<<BDIM, 256>>>(Xbuf, c0, ac, bc, hx, cx, Hxc);

    gemm_single<<<256, 128, GEMM_SMEM>>>(Hxc, Wd, bdec, out, HDIM, 1024);
}

// round 17
// speedup vs baseline: 1.3790x; 1.3790x over previous
#include <cuda_runtime.h>
#include <cuda_bf16.h>
#include <stdint.h>
#include <math.h>

// ---------------------------------------------------------------------------
// LN-LSTM cell.  B=4096, IN=1024, H=2048, OUT=1024.
// GEMMs via mma.sync bf16 (HMMA), split precision [hi|lo] (2K) + 3-pass remap
// (R12-proven).  GEMM config: 128x128x64 CTA tile, 256 thr (2x4 warps of
// 64x32), 3-stage cp.async, 2 CTA/SM — R14-proven local optimum, untouched.
// R16: revert R15's 4-warp experiment; __expf/__fdividef in elementwise.
// ---------------------------------------------------------------------------

#define BDIM 4096
#define HDIM 2048
#define EPS_LN 1e-5f

__device__ float g_Xbuf[(size_t)BDIM * 4 * HDIM];
__device__ float g_Hbuf[(size_t)BDIM * 4 * HDIM];
__device__ __nv_bfloat16 g_Ax[(size_t)BDIM * 2 * 1024];
__device__ __nv_bfloat16 g_Ah[(size_t)BDIM * 2 * HDIM];
__device__ __nv_bfloat16 g_Wx[(size_t)4 * HDIM * 2 * 1024];
__device__ __nv_bfloat16 g_Wh[(size_t)4 * HDIM * 2 * HDIM];
__device__ __nv_bfloat16 g_Wd[(size_t)1024 * 2 * HDIM];
__device__ __nv_bfloat16 g_Hxc[(size_t)BDIM * 2 * HDIM];
__device__ float g_biasx[4 * HDIM];
__device__ float g_biash[4 * HDIM];

// ------------------------------- helpers -----------------------------------
__device__ __forceinline__ uint32_t smem_u32(const void* p) {
    uint32_t a;
    asm("{ .reg .u64 t; cvta.to.shared.u64 t, %1; cvt.u32.u64 %0, t; }" : "=r"(a) : "l"(p));
    return a;
}
#define CP_ASYNC16(dst, src) \
    asm volatile("cp.async.cg.shared.global [%0], [%1], 16;" :: "r"(dst), "l"(src) : "memory")
#define CP_COMMIT()  asm volatile("cp.async.commit_group;" ::: "memory")
#define CP_WAIT1()   asm volatile("cp.async.wait_group 1;" ::: "memory")

__device__ __forceinline__ float fast_sig(float x) {
    return __fdividef(1.0f, 1.0f + __expf(-x));
}

__device__ __forceinline__ uint32_t pack_bf2(float a, float b) {
    const uint32_t ua = (uint32_t)__bfloat16_as_ushort(__float2bfloat16(a));
    const uint32_t ub = (uint32_t)__bfloat16_as_ushort(__float2bfloat16(b));
    return ua | (ub << 16);
}
__device__ __forceinline__ void split4(const float4 x, uint2& hi, uint2& lo) {
    const __nv_bfloat16 h0 = __float2bfloat16(x.x), h1 = __float2bfloat16(x.y);
    const __nv_bfloat16 h2 = __float2bfloat16(x.z), h3 = __float2bfloat16(x.w);
    hi.x = (uint32_t)__bfloat16_as_ushort(h0) | ((uint32_t)__bfloat16_as_ushort(h1) << 16);
    hi.y = (uint32_t)__bfloat16_as_ushort(h2) | ((uint32_t)__bfloat16_as_ushort(h3) << 16);
    lo.x = pack_bf2(x.x - __bfloat162float(h0), x.y - __bfloat162float(h1));
    lo.y = pack_bf2(x.z - __bfloat162float(h2), x.w - __bfloat162float(h3));
}

// ---------------------------------------------------------------------------
// HMMA GEMM body (R14-proven: 256 thr, 2x4 warps of 64x32, 3-stage).
// A is [M, 2*K0] = [hi|lo]; W is [Ntot, 2*K0] = [hi|lo]; 3-pass K remap.
// ---------------------------------------------------------------------------
#define BM 128
#define BN 128
#define BK 64
#define NSTG 3
#define STG_BYTES 32768                 // A(16KB) + B(16KB)
#define GEMM_SMEM (NSTG * STG_BYTES)    // 98304

__device__ __forceinline__ void gemm_body(
    const __nv_bfloat16* __restrict__ A, const __nv_bfloat16* __restrict__ W,
    const float* __restrict__ bias, float* __restrict__ C, int K0, int Ntot,
    int bm, int bn)
{
    extern __shared__ char smem[];
    const uint32_t sb = smem_u32(smem);
    const int tid  = threadIdx.x;
    const int lane = tid & 31, wid = tid >> 5;
    const int wm = wid & 1, wn = wid >> 1;            // warp grid 2 x 4
    const int m0 = bm * BM, n0 = bn * BN;
    const int K0B = K0 / BK;
    const int nkt = 3 * K0B;
    const int Kcat = 2 * K0;

    const int lrow  = tid >> 1;
    const int lhalf = tid & 1;
    const __nv_bfloat16* agp = A + (size_t)(m0 + lrow) * Kcat + lhalf * 32;
    const __nv_bfloat16* bgp = W + (size_t)(n0 + lrow) * Kcat + lhalf * 32;

#define LOADT(kt, stg) do {                                                     \
    const int _p = (kt) / K0B, _r = (kt) - _p * K0B;                            \
    const int _ak = (_p == 1) ? K0B + _r : _r;                                  \
    const int _wk = (_p == 2) ? K0B + _r : _r;                                  \
    const __nv_bfloat16* a_ = agp + (size_t)_ak * BK;                           \
    const __nv_bfloat16* b_ = bgp + (size_t)_wk * BK;                           \
    const uint32_t as_ = sb + (stg) * STG_BYTES;                                \
    const uint32_t bs_ = as_ + 16384;                                           \
    _Pragma("unroll")                                                           \
    for (int j = 0; j < 4; j++) {                                               \
        const uint32_t g   = lhalf * 4 + j;                                     \
        const uint32_t off = lrow * 128 + ((g ^ (lrow & 7)) << 4);              \
        CP_ASYNC16(as_ + off, a_ + j * 8);                                      \
        CP_ASYNC16(bs_ + off, b_ + j * 8);                                      \
    }                                                                           \
} while (0)

    const int a_r16 = lane & 15;
    const int a_h   = lane >> 4;
    const int b_sel = lane >> 3, b_tr = lane & 7;
    const int b_roff = ((b_sel >> 1) & 1) * 8 + b_tr;
    const int b_h    = b_sel & 1;

    float acc[4][4][4];
    #pragma unroll
    for (int i = 0; i < 4; i++)
        #pragma unroll
        for (int j = 0; j < 4; j++)
            #pragma unroll
            for (int q = 0; q < 4; q++) acc[i][j][q] = 0.0f;

    LOADT(0, 0); CP_COMMIT();
    LOADT(1, 1); CP_COMMIT();

    for (int kt = 0; kt < nkt; kt++) {
        const int stg = kt % NSTG;
        CP_WAIT1();
        __syncthreads();
        const uint32_t as_ = sb + stg * STG_BYTES;
        const uint32_t bs_ = as_ + 16384;

        #pragma unroll
        for (int kk = 0; kk < 4; kk++) {
            uint32_t a[4][4], b[2][4];
            #pragma unroll
            for (int mf = 0; mf < 4; mf++) {
                const int r = wm * 64 + mf * 16 + a_r16;
                const uint32_t ad = as_ + r * 128 + (((kk * 2 + a_h) ^ (r & 7)) << 4);
                asm volatile("ldmatrix.sync.aligned.m8n8.x4.shared.b16 {%0,%1,%2,%3}, [%4];"
                    : "=r"(a[mf][0]), "=r"(a[mf][1]), "=r"(a[mf][2]), "=r"(a[mf][3])
                    : "r"(ad));
            }
            #pragma unroll
            for (int p = 0; p < 2; p++) {
                const int r = wn * 32 + p * 16 + b_roff;
                const uint32_t bd = bs_ + r * 128 + (((kk * 2 + b_h) ^ (r & 7)) << 4);
                asm volatile("ldmatrix.sync.aligned.m8n8.x4.shared.b16 {%0,%1,%2,%3}, [%4];"
                    : "=r"(b[p][0]), "=r"(b[p][1]), "=r"(b[p][2]), "=r"(b[p][3])
                    : "r"(bd));
            }
            #pragma unroll
            for (int mf = 0; mf < 4; mf++)
                #pragma unroll
                for (int nf = 0; nf < 4; nf++) {
                    const uint32_t b0 = b[nf >> 1][(nf & 1) * 2 + 0];
                    const uint32_t b1 = b[nf >> 1][(nf & 1) * 2 + 1];
                    asm volatile(
                        "mma.sync.aligned.m16n8k16.row.col.f32.bf16.bf16.f32 "
                        "{%0,%1,%2,%3}, {%4,%5,%6,%7}, {%8,%9}, {%0,%1,%2,%3};"
                        : "+f"(acc[mf][nf][0]), "+f"(acc[mf][nf][1]),
                          "+f"(acc[mf][nf][2]), "+f"(acc[mf][nf][3])
                        : "r"(a[mf][0]), "r"(a[mf][1]), "r"(a[mf][2]), "r"(a[mf][3]),
                          "r"(b0), "r"(b1));
                }
        }
        if (kt + NSTG - 1 < nkt) LOADT(kt + NSTG - 1, (kt + NSTG - 1) % NSTG);
        CP_COMMIT();
    }

    const int er = lane >> 2, ec = (lane & 3) * 2;
    #pragma unroll
    for (int mf = 0; mf < 4; mf++) {
        const int grow = m0 + wm * 64 + mf * 16 + er;
        #pragma unroll
        for (int nf = 0; nf < 4; nf++) {
            const int gcol = n0 + wn * 32 + nf * 8 + ec;
            const float bx0 = __ldg(bias + gcol), bx1 = __ldg(bias + gcol + 1);
            float2 v0 = make_float2(acc[mf][nf][0] + bx0, acc[mf][nf][1] + bx1);
            float2 v1 = make_float2(acc[mf][nf][2] + bx0, acc[mf][nf][3] + bx1);
            *(float2*)&C[(size_t)grow * Ntot + gcol] = v0;
            *(float2*)&C[(size_t)(grow + 8) * Ntot + gcol] = v1;
        }
    }
#undef LOADT
}

__global__ void __launch_bounds__(256, 2) gemm_dual(
    const __nv_bfloat16* __restrict__ Ah, const __nv_bfloat16* __restrict__ Wh,
    const float* __restrict__ biash, float* __restrict__ Hbuf,
    const __nv_bfloat16* __restrict__ Ax, const __nv_bfloat16* __restrict__ Wx,
    const float* __restrict__ biasx, float* __restrict__ Xbuf)
{
    int idx = blockIdx.x;
    if (idx < 2048) {
        gemm_body(Ah, Wh, biash, Hbuf, HDIM, 4 * HDIM, idx & 31, idx >> 5);
    } else {
        idx -= 2048;
        gemm_body(Ax, Wx, biasx, Xbuf, 1024, 4 * HDIM, idx & 31, idx >> 5);
    }
}

__global__ void __launch_bounds__(256, 2) gemm_single(
    const __nv_bfloat16* __restrict__ A, const __nv_bfloat16* __restrict__ W,
    const float* __restrict__ bias, float* __restrict__ C, int K0, int Ntot)
{
    const int idx = blockIdx.x;
    gemm_body(A, W, bias, C, K0, Ntot, idx & 31, idx >> 5);
}

// ---------------------------------------------------------------------------
// Prep: all fp32 -> bf16 [hi|lo] splits + bias concats, float4 vectorized.
// ---------------------------------------------------------------------------
#define PREP_BLOCKS 25664

__device__ __forceinline__ void split_row_v4(
    const float* __restrict__ src, __nv_bfloat16* __restrict__ d, int K)
{
    for (int c = threadIdx.x * 4; c < K; c += 1024) {
        const float4 x = *(const float4*)(src + c);
        uint2 hi, lo;
        split4(x, hi, lo);
        *(uint2*)(d + c) = hi;
        *(uint2*)(d + K + c) = lo;
    }
}

__global__ void __launch_bounds__(256) prep_kernel(
    const float* __restrict__ inp, const float* __restrict__ h0,
    const float* __restrict__ Wdec,
    const float* __restrict__ Wfx, const float* __restrict__ Wix,
    const float* __restrict__ Wcx, const float* __restrict__ Wox,
    const float* __restrict__ Wfh, const float* __restrict__ Wih,
    const float* __restrict__ Wch, const float* __restrict__ Woh,
    const float* __restrict__ bfx, const float* __restrict__ bix,
    const float* __restrict__ bcx, const float* __restrict__ box_,
    const float* __restrict__ bfh, const float* __restrict__ bih,
    const float* __restrict__ bch, const float* __restrict__ boh,
    __nv_bfloat16* __restrict__ Ax, __nv_bfloat16* __restrict__ Ah,
    __nv_bfloat16* __restrict__ Wd, __nv_bfloat16* __restrict__ Wx,
    __nv_bfloat16* __restrict__ Wh,
    float* __restrict__ biasx, float* __restrict__ biash)
{
    int b = blockIdx.x;
    if (b < 4096) {
        split_row_v4(inp + (size_t)b * 1024, Ax + (size_t)b * 2048, 1024);
        return;
    }
    b -= 4096;
    if (b < 4096) {
        split_row_v4(h0 + (size_t)b * 2048, Ah + (size_t)b * 4096, 2048);
        return;
    }
    b -= 4096;
    if (b < 1024) {
        split_row_v4(Wdec + (size_t)b * 2048, Wd + (size_t)b * 4096, 2048);
        return;
    }
    b -= 1024;
    if (b < 8192) {
        const int gate = b >> 11, row = b & 2047;
        const float* w = (gate == 0) ? Wfx : (gate == 1) ? Wix : (gate == 2) ? Wcx : Wox;
        split_row_v4(w + (size_t)row * 1024, Wx + (size_t)b * 2048, 1024);
        return;
    }
    b -= 8192;
    if (b < 8192) {
        const int gate = b >> 11, row = b & 2047;
        const float* w = (gate == 0) ? Wfh : (gate == 1) ? Wih : (gate == 2) ? Wch : Woh;
        split_row_v4(w + (size_t)row * 2048, Wh + (size_t)b * 4096, 2048);
        return;
    }
    b -= 8192;
    if (b < 32) {
        const int i = b * 256 + threadIdx.x;
        const int g = i >> 11, c = i & 2047;
        biasx[i] = (g == 0) ? bfx[c] : (g == 1) ? bix[c] : (g == 2) ? bcx[c] : box_[c];
        return;
    }
    b -= 32;
    {
        const int i = b * 256 + threadIdx.x;
        const int g = i >> 11, c = i & 2047;
        biash[i] = (g == 0) ? bfh[c] : (g == 1) ? bih[c] : (g == 2) ? bch[c] : boh[c];
    }
}

// ---------------------------------------------------------------------------
// LN combine (float4): G = LN(X;ax,bx) + LN(H;ah,bh), in place into Xbuf.
// ---------------------------------------------------------------------------
__global__ void __launch_bounds__(256) ln_combine_kernel(
    float* __restrict__ Xbuf, const float* __restrict__ Hbuf,
    const float* __restrict__ ax, const float* __restrict__ bxv,
    const float* __restrict__ ah, const float* __restrict__ bhv)
{
    const int row = blockIdx.x, gate = blockIdx.y, tid = threadIdx.x;
    const size_t base = (size_t)row * (4 * HDIM) + (size_t)gate * HDIM;

    float4 x[2], h[2];
    float sx = 0.f, sxx = 0.f, sh = 0.f, shh = 0.f;
    #pragma unroll
    for (int i = 0; i < 2; i++) {
        const int c = i * 1024 + tid * 4;
        x[i] = *(const float4*)(Xbuf + base + c);
        h[i] = *(const float4*)(Hbuf + base + c);
        sx += x[i].x + x[i].y + x[i].z + x[i].w;
        sxx += x[i].x * x[i].x + x[i].y * x[i].y + x[i].z * x[i].z + x[i].w * x[i].w;
        sh += h[i].x + h[i].y + h[i].z + h[i].w;
        shh += h[i].x * h[i].x + h[i].y * h[i].y + h[i].z * h[i].z + h[i].w * h[i].w;
    }
    __shared__ float4 red[256];
    red[tid] = make_float4(sx, sxx, sh, shh);
    __syncthreads();
    #pragma unroll
    for (int s = 128; s > 0; s >>= 1) {
        if (tid < s) {
            float4 o = red[tid + s], m = red[tid];
            red[tid] = make_float4(m.x + o.x, m.y + o.y, m.z + o.z, m.w + o.w);
        }
        __syncthreads();
    }
    const float4 t = red[0];
    const float n = (float)HDIM;
    const float mux = t.x / n, muh = t.z / n;
    const float vx = (t.y - n * mux * mux) / (n - 1.0f);
    const float vh = (t.w - n * muh * muh) / (n - 1.0f);
    const float rx = 1.0f / (sqrtf(fmaxf(vx, 0.f)) + EPS_LN);
    const float rh = 1.0f / (sqrtf(fmaxf(vh, 0.f)) + EPS_LN);
    #pragma unroll
    for (int i = 0; i < 2; i++) {
        const int c = i * 1024 + tid * 4;
        const float4 a4 = *(const float4*)(ax + c);
        const float4 b4 = *(const float4*)(bxv + c);
        const float4 a4h = *(const float4*)(ah + c);
        const float4 b4h = *(const float4*)(bhv + c);
        float4 g;
        g.x = (x[i].x - mux) * rx * a4.x + b4.x + (h[i].x - muh) * rh * a4h.x + b4h.x;
        g.y = (x[i].y - mux) * rx * a4.y + b4.y + (h[i].y - muh) * rh * a4h.y + b4h.y;
        g.z = (x[i].z - mux) * rx * a4.z + b4.z + (h[i].z - muh) * rh * a4h.z + b4h.z;
        g.w = (x[i].w - mux) * rx * a4.w + b4.w + (h[i].w - muh) * rh * a4h.w + b4h.w;
        *(float4*)(Xbuf + base + c) = g;
    }
}

// ---------------------------------------------------------------------------
// Cell (float4): gates -> cx, row-LN(cx), hx; emits hx split [hi|lo] bf16.
// ---------------------------------------------------------------------------
__global__ void __launch_bounds__(256) cell_kernel(
    const float* __restrict__ G, const float* __restrict__ c0,
    const float* __restrict__ ac, const float* __restrict__ bcv,
    float* __restrict__ hx_out, float* __restrict__ cx_out,
    __nv_bfloat16* __restrict__ hxcat)
{
    const int row = blockIdx.x, tid = threadIdx.x;
    const size_t base = (size_t)row * (4 * HDIM);

    float4 cv[2], og[2];
    float s = 0.f, ss = 0.f;
    #pragma unroll
    for (int i = 0; i < 2; i++) {
        const int c = i * 1024 + tid * 4;
        const float4 gf = *(const float4*)(G + base + c);
        const float4 gi = *(const float4*)(G + base + HDIM + c);
        const float4 gc = *(const float4*)(G + base + 2 * HDIM + c);
        const float4 go = *(const float4*)(G + base + 3 * HDIM + c);
        const float4 cz = *(const float4*)(c0 + (size_t)row * HDIM + c);
        float4 v;
        v.x = fast_sig(gf.x) * cz.x + fast_sig(gi.x) * tanhf(gc.x);
        v.y = fast_sig(gf.y) * cz.y + fast_sig(gi.y) * tanhf(gc.y);
        v.z = fast_sig(gf.z) * cz.z + fast_sig(gi.z) * tanhf(gc.z);
        v.w = fast_sig(gf.w) * cz.w + fast_sig(gi.w) * tanhf(gc.w);
        cv[i] = v; og[i] = go;
        s += v.x + v.y + v.z + v.w;
        ss += v.x * v.x + v.y * v.y + v.z * v.z + v.w * v.w;
    }
    __shared__ float2 red[256];
    red[tid] = make_float2(s, ss);
    __syncthreads();
    #pragma unroll
    for (int st = 128; st > 0; st >>= 1) {
        if (tid < st) {
            float2 o = red[tid + st], m = red[tid];
            red[tid] = make_float2(m.x + o.x, m.y + o.y);
        }
        __syncthreads();
    }
    const float2 t = red[0];
    const float n = (float)HDIM;
    const float mu = t.x / n;
    const float var = (t.y - n * mu * mu) / (n - 1.0f);
    const float rs = 1.0f / (sqrtf(fmaxf(var, 0.f)) + EPS_LN);

    __nv_bfloat16* hrow = hxcat + (size_t)row * (2 * HDIM);
    #pragma unroll
    for (int i = 0; i < 2; i++) {
        const int c = i * 1024 + tid * 4;
        const float4 a4 = *(const float4*)(ac + c);
        const float4 b4 = *(const float4*)(bcv + c);
        float4 hv;
        hv.x = fast_sig(og[i].x) * tanhf((cv[i].x - mu) * rs * a4.x + b4.x);
        hv.y = fast_sig(og[i].y) * tanhf((cv[i].y - mu) * rs * a4.y + b4.y);
        hv.z = fast_sig(og[i].z) * tanhf((cv[i].z - mu) * rs * a4.z + b4.z);
        hv.w = fast_sig(og[i].w) * tanhf((cv[i].w - mu) * rs * a4.w + b4.w);
        *(float4*)(hx_out + (size_t)row * HDIM + c) = hv;
        *(float4*)(cx_out + (size_t)row * HDIM + c) = cv[i];
        uint2 hi, lo;
        split4(hv, hi, lo);
        *(uint2*)(hrow + c) = hi;
        *(uint2*)(hrow + HDIM + c) = lo;
    }
}

// ---------------------------------------------------------------------------
extern "C" void kernel_launch(void* const* d_in, const int* in_sizes, int n_in,
                              void* d_out, int out_size)
{
    (void)in_sizes; (void)n_in; (void)out_size;
    const float* inp = (const float*)d_in[0];
    const float* h0  = (const float*)d_in[1];
    const float* c0  = (const float*)d_in[2];
    const float* Wfh = (const float*)d_in[3];   const float* bfh = (const float*)d_in[4];
    const float* Wih = (const float*)d_in[5];   const float* bih = (const float*)d_in[6];
    const float* Wch = (const float*)d_in[7];   const float* bch = (const float*)d_in[8];
    const float* Woh = (const float*)d_in[9];   const float* boh = (const float*)d_in[10];
    const float* Wfx = (const float*)d_in[11];  const float* bfx = (const float*)d_in[12];
    const float* Wix = (const float*)d_in[13];  const float* bix = (const float*)d_in[14];
    const float* Wcx = (const float*)d_in[15];  const float* bcx = (const float*)d_in[16];
    const float* Wox = (const float*)d_in[17];  const float* box_ = (const float*)d_in[18];
    const float* Wdec = (const float*)d_in[19]; const float* bdec = (const float*)d_in[20];
    const float* ax = (const float*)d_in[21];   const float* bx = (const float*)d_in[22];
    const float* ah = (const float*)d_in[23];   const float* bh = (const float*)d_in[24];
    const float* ac = (const float*)d_in[25];   const float* bc = (const float*)d_in[26];

    float *Xbuf, *Hbuf, *biasx, *biash;
    __nv_bfloat16 *Ax, *Ah, *Wx, *Wh, *Wd, *Hxc;
    cudaGetSymbolAddress((void**)&Xbuf, g_Xbuf);
    cudaGetSymbolAddress((void**)&Hbuf, g_Hbuf);
    cudaGetSymbolAddress((void**)&Ax, g_Ax);
    cudaGetSymbolAddress((void**)&Ah, g_Ah);
    cudaGetSymbolAddress((void**)&Wx, g_Wx);
    cudaGetSymbolAddress((void**)&Wh, g_Wh);
    cudaGetSymbolAddress((void**)&Wd, g_Wd);
    cudaGetSymbolAddress((void**)&Hxc, g_Hxc);
    cudaGetSymbolAddress((void**)&biasx, g_biasx);
    cudaGetSymbolAddress((void**)&biash, g_biash);

    cudaFuncSetAttribute(gemm_dual,   cudaFuncAttributeMaxDynamicSharedMemorySize, GEMM_SMEM);
    cudaFuncSetAttribute(gemm_single, cudaFuncAttributeMaxDynamicSharedMemorySize, GEMM_SMEM);

    float* out = (float*)d_out;
    float* hx  = out + (size_t)BDIM * 1024;
    float* cx  = hx + (size_t)BDIM * HDIM;

    prep_kernel<<<PREP_BLOCKS, 256>>>(
        inp, h0, Wdec,
        Wfx, Wix, Wcx, Wox, Wfh, Wih, Wch, Woh,
        bfx, bix, bcx, box_, bfh, bih, bch, boh,
        Ax, Ah, Wd, Wx, Wh, biasx, biash);

    gemm_dual<<<4096, 256, GEMM_SMEM>>>(
        Ah, Wh, biash, Hbuf, Ax, Wx, biasx, Xbuf);

    ln_combine_kernel<<<dim3(BDIM, 4), 256>>>(Xbuf, Hbuf, ax, bx, ah, bh);
    cell_kernel<<<BDIM, 256>>>(Xbuf, c0, ac, bc, hx, cx, Hxc);

    gemm_single<<<256, 256, GEMM_SMEM>>>(Hxc, Wd, bdec, out, HDIM, 1024);
}